// round 6
// baseline (speedup 1.0000x reference)
#include <cuda_runtime.h>
#include <math.h>

// ---------------------------------------------------------------------------
// CATB axial attention block. fp32, FFMA2 (f32x2) everywhere hot.
// R5: attention = 12 warps/block, fused QK->exp->AV (no max tracking).
// ---------------------------------------------------------------------------

#define BATCH 2
#define HH 112
#define WW 112
#define CC 192
#define LL (HH * WW)          // 12544
#define MROWS (BATCH * LL)    // 25088
#define CB 96
#define HD_ 24
#define NTOK 784              // 112*7
#define NPOS 2899             // (2*112-1)*(2*7-1)
#define HIDDEN 768

typedef unsigned long long u64;

// -------------------------- scratch (device globals) -----------------------
__device__ float g_img[MROWS * CC];
__device__ float g_qkv[MROWS * 3 * CC];
__device__ float g_att[MROWS * CC];
__device__ float g_xo [MROWS * CC];
__device__ float g_y  [MROWS * CC];
__device__ float g_h  [MROWS * HIDDEN];
__device__ float g_pos[2 * NPOS * 4];

// -------------------------- f32x2 helpers ----------------------------------
__device__ __forceinline__ void ffma2(u64& c, u64 a, u64 b)
{
    asm("fma.rn.f32x2 %0, %1, %2, %0;" : "+l"(c) : "l"(a), "l"(b));
}
__device__ __forceinline__ u64 pack2(float lo, float hi)
{
    u64 r;
    asm("mov.b64 %0, {%1, %2};" : "=l"(r) : "f"(lo), "f"(hi));
    return r;
}
__device__ __forceinline__ float lo2(u64 v) { return __uint_as_float((unsigned)v); }
__device__ __forceinline__ float hi2(u64 v) { return __uint_as_float((unsigned)(v >> 32)); }

// -------------------------- LayerNorm over C=192 ---------------------------
__global__ __launch_bounds__(256) void ln_kernel(
    const float* __restrict__ in, const float* __restrict__ w,
    const float* __restrict__ b, float* __restrict__ out)
{
    int row = blockIdx.x * 8 + (threadIdx.x >> 5);
    if (row >= MROWS) return;
    int lane = threadIdx.x & 31;
    const float* p = in + (long)row * CC;
    float v[6];
    float s = 0.f, s2 = 0.f;
#pragma unroll
    for (int u = 0; u < 6; u++) {
        v[u] = p[lane + u * 32];
        s += v[u];
        s2 += v[u] * v[u];
    }
#pragma unroll
    for (int off = 16; off > 0; off >>= 1) {
        s  += __shfl_xor_sync(0xffffffffu, s,  off);
        s2 += __shfl_xor_sync(0xffffffffu, s2, off);
    }
    float mu  = s * (1.f / CC);
    float var = s2 * (1.f / CC) - mu * mu;
    float inv = rsqrtf(var + 1e-5f);
    float* q = out + (long)row * CC;
#pragma unroll
    for (int u = 0; u < 6; u++) {
        int c = lane + u * 32;
        q[c] = (v[u] - mu) * inv * w[c] + b[c];
    }
}

// -------------------------- rel-pos-bias MLP -------------------------------
__device__ __forceinline__ void ln6_relu(float* v, const float* w, const float* b)
{
    float mu = 0.f;
#pragma unroll
    for (int i = 0; i < 6; i++) mu += v[i];
    mu *= (1.f / 6.f);
    float var = 0.f;
#pragma unroll
    for (int i = 0; i < 6; i++) { float d = v[i] - mu; var += d * d; }
    var *= (1.f / 6.f);
    float inv = rsqrtf(var + 1e-5f);
#pragma unroll
    for (int i = 0; i < 6; i++)
        v[i] = fmaxf((v[i] - mu) * inv * w[i] + b[i], 0.f);
}

__global__ void pos_mlp_kernel(
    const float* __restrict__ proj_w, const float* __restrict__ proj_b,
    const float* __restrict__ ln1_w,  const float* __restrict__ ln1_b,
    const float* __restrict__ fc1_w,  const float* __restrict__ fc1_b,
    const float* __restrict__ ln2_w,  const float* __restrict__ ln2_b,
    const float* __restrict__ fc2_w,  const float* __restrict__ fc2_b,
    const float* __restrict__ ln3_w,  const float* __restrict__ ln3_b,
    const float* __restrict__ fc3_w,  const float* __restrict__ fc3_b,
    float* __restrict__ out)
{
    int idx = blockIdx.x * blockDim.x + threadIdx.x;
    if (idx >= 2 * NPOS) return;
    int br = idx / NPOS, r = idx - br * NPOS;
    int Hsp = br ? 7 : 112;
    int Wsp = br ? 112 : 7;
    int W2 = 2 * Wsp - 1;
    int a = r / W2, bcol = r - a * W2;
    float ph = (float)(a - (Hsp - 1));
    float pw = (float)(bcol - (Wsp - 1));

    float t[6], u[6];
#pragma unroll
    for (int o = 0; o < 6; o++)
        t[o] = proj_w[(br * 6 + o) * 2 + 0] * ph +
               proj_w[(br * 6 + o) * 2 + 1] * pw + proj_b[br * 6 + o];
    ln6_relu(t, ln1_w + br * 6, ln1_b + br * 6);
#pragma unroll
    for (int o = 0; o < 6; o++) {
        float s = fc1_b[br * 6 + o];
#pragma unroll
        for (int i = 0; i < 6; i++) s += fc1_w[br * 36 + o * 6 + i] * t[i];
        u[o] = s;
    }
    ln6_relu(u, ln2_w + br * 6, ln2_b + br * 6);
#pragma unroll
    for (int o = 0; o < 6; o++) {
        float s = fc2_b[br * 6 + o];
#pragma unroll
        for (int i = 0; i < 6; i++) s += fc2_w[br * 36 + o * 6 + i] * u[i];
        t[o] = s;
    }
    ln6_relu(t, ln3_w + br * 6, ln3_b + br * 6);
#pragma unroll
    for (int h = 0; h < 4; h++) {
        float s = fc3_b[br * 4 + h];
#pragma unroll
        for (int i = 0; i < 6; i++) s += fc3_w[br * 24 + h * 6 + i] * t[i];
        out[(br * NPOS + r) * 4 + h] = s;
    }
}

// -------------------------- attention --------------------------------------
// 256 blocks = (branch, window, head), 384 threads (12 warps).
// Lanes own query rows; K/V rows broadcast from SMEM. Fused QK->exp->AV,
// no max subtraction (scores are bounded; exp cannot overflow fp32).
#define ATTN_SMEM ((2 * NTOK * HD_ + NPOS + NTOK) * 4)
#define ATHR 384

template <int ROWS>
__device__ __forceinline__ void attn_pass(
    int start, int lane, int br, int b, int w16, int cbase,
    const float* __restrict__ qkv, const float* Ks, const float* Vs,
    const float* Ps, const int* Rj, float* __restrict__ att_out)
{
    const float scale = 0.20412414523193154f; // 24^-0.5
    const int Hsp = br ? 7 : 112;
    const int Wsp = br ? 112 : 7;
    const int W2  = 2 * Wsp - 1;

    int rA = start + lane;
    bool actA = rA < NTOK;
    int rAc = actA ? rA : NTOK - 1;
    int rB = rA + 32;
    bool actB = (ROWS == 2) && (rB < NTOK);
    int rBc = actB ? rB : NTOK - 1;

    int hiA, wiA, lA, hiB, wiB, lB;
    if (br == 0) {
        hiA = rAc / 7;  wiA = rAc - hiA * 7;  lA = hiA * WW + w16 * 7 + wiA;
        hiB = rBc / 7;  wiB = rBc - hiB * 7;  lB = hiB * WW + w16 * 7 + wiB;
    } else {
        hiA = rAc / 112; wiA = rAc - hiA * 112; lA = (w16 * 7 + hiA) * WW + wiA;
        hiB = rBc / 112; wiB = rBc - hiB * 112; lB = (w16 * 7 + hiB) * WW + wiB;
    }
    int rbA = (hiA + Hsp - 1) * W2 + wiA + Wsp - 1;
    int rbB = (hiB + Hsp - 1) * W2 + wiB + Wsp - 1;

    u64 qA[12], qB[12];
    {
        const float* qp = qkv + ((long)(b * LL + lA)) * 576 + cbase;
#pragma unroll
        for (int d = 0; d < 12; d++)
            qA[d] = pack2(qp[2 * d] * scale, qp[2 * d + 1] * scale);
    }
    if (ROWS == 2) {
        const float* qp = qkv + ((long)(b * LL + lB)) * 576 + cbase;
#pragma unroll
        for (int d = 0; d < 12; d++)
            qB[d] = pack2(qp[2 * d] * scale, qp[2 * d + 1] * scale);
    }

    float eA = 0.f, eB = 0.f;
    u64 OA[12], OB[12];
#pragma unroll
    for (int d = 0; d < 12; d++) { OA[d] = 0ull; OB[d] = 0ull; }

#pragma unroll 4
    for (int j = 0; j < NTOK; j++) {
        const ulonglong2* kp = (const ulonglong2*)(Ks + j * HD_);
        u64 psA = 0ull, psB = 0ull;
#pragma unroll
        for (int i = 0; i < 6; i++) {
            ulonglong2 kk = kp[i];
            ffma2(psA, kk.x, qA[2 * i]);
            ffma2(psA, kk.y, qA[2 * i + 1]);
            if (ROWS == 2) {
                ffma2(psB, kk.x, qB[2 * i]);
                ffma2(psB, kk.y, qB[2 * i + 1]);
            }
        }
        int roff = Rj[j];
        float pA = __expf(lo2(psA) + hi2(psA) + Ps[rbA - roff]);
        eA += pA;
        u64 pAd = pack2(pA, pA);
        float pB = 0.f; u64 pBd = 0ull;
        if (ROWS == 2) {
            pB = __expf(lo2(psB) + hi2(psB) + Ps[rbB - roff]);
            eB += pB;
            pBd = pack2(pB, pB);
        }
        const ulonglong2* vp = (const ulonglong2*)(Vs + j * HD_);
#pragma unroll
        for (int i = 0; i < 6; i++) {
            ulonglong2 vv = vp[i];
            ffma2(OA[2 * i],     vv.x, pAd);
            ffma2(OA[2 * i + 1], vv.y, pAd);
            if (ROWS == 2) {
                ffma2(OB[2 * i],     vv.x, pBd);
                ffma2(OB[2 * i + 1], vv.y, pBd);
            }
        }
    }
    if (actA) {
        float inv = 1.f / eA;
        float* o = att_out + ((long)(b * LL + lA)) * CC + cbase;
#pragma unroll
        for (int i = 0; i < 6; i++) {
            u64 a = OA[2 * i], c = OA[2 * i + 1];
            *(float4*)(o + i * 4) = make_float4(lo2(a) * inv, hi2(a) * inv,
                                                lo2(c) * inv, hi2(c) * inv);
        }
    }
    if (ROWS == 2 && actB) {
        float inv = 1.f / eB;
        float* o = att_out + ((long)(b * LL + lB)) * CC + cbase;
#pragma unroll
        for (int i = 0; i < 6; i++) {
            u64 a = OB[2 * i], c = OB[2 * i + 1];
            *(float4*)(o + i * 4) = make_float4(lo2(a) * inv, hi2(a) * inv,
                                                lo2(c) * inv, hi2(c) * inv);
        }
    }
}

__global__ __launch_bounds__(ATHR) void attn_kernel(
    const float* __restrict__ qkv, const float* __restrict__ pos,
    float* __restrict__ att_out)
{
    extern __shared__ float sm[];
    float* Ks = sm;                          // 784*24
    float* Vs = Ks + NTOK * HD_;             // 784*24
    float* Ps = Vs + NTOK * HD_;             // 2899
    int*   Rj = (int*)(Ps + NPOS);           // 784

    int bx   = blockIdx.x;
    int br   = bx >> 7;
    int rem  = bx & 127;
    int win  = rem >> 2;
    int head = rem & 3;
    int b    = win >> 4, w16 = win & 15;
    int tid  = threadIdx.x, lane = tid & 31, warp = tid >> 5;
    int cbase = br * CB + head * HD_;

    const int W2 = br ? (2 * WW - 1) : 13;

    for (int idx = tid; idx < NTOK * HD_; idx += ATHR) {
        int j = idx / HD_, d = idx - j * HD_;
        int h, w;
        if (br == 0) { int hj = j / 7;   h = hj;           w = w16 * 7 + (j - hj * 7); }
        else         { int hj = j / 112; h = w16 * 7 + hj; w = j - hj * 112; }
        long base = ((long)(b * LL + h * WW + w)) * 576 + cbase + d;
        Ks[j * HD_ + d] = qkv[base + 192];
        Vs[j * HD_ + d] = qkv[base + 384];
    }
    for (int rr = tid; rr < NPOS; rr += ATHR)
        Ps[rr] = pos[(br * NPOS + rr) * 4 + head];
    for (int j = tid; j < NTOK; j += ATHR) {
        int hj, wj;
        if (br == 0) { hj = j / 7;   wj = j - hj * 7;   }
        else         { hj = j / 112; wj = j - hj * 112; }
        Rj[j] = hj * W2 + wj;
    }
    __syncthreads();

    // 12 warps: warp w handles rows [w*64, w*64+64); warp 11 also rows 768..783
    attn_pass<2>(warp * 64, lane, br, b, w16, cbase, qkv, Ks, Vs, Ps, Rj, att_out);
    if (warp == 11)
        attn_pass<1>(768, lane, br, b, w16, cbase, qkv, Ks, Vs, Ps, Rj, att_out);
}

// -------------------------- SGEMM (NT) with FFMA2 --------------------------
// out[M,N] = A[M,K] @ W[N,K]^T. BM=128, BN=64, BK=16, 256 thr.
// Conflict-free SMEM layout; b duplicated into register pairs.
__device__ __forceinline__ float gelu_f(float x)
{
    return 0.5f * x * (1.f + erff(x * 0.7071067811865476f));
}

template <int MODE>
__global__ __launch_bounds__(256) void gemm_kernel(
    const float* __restrict__ A, const float* __restrict__ Wt,
    const float* __restrict__ bias, const float* __restrict__ res,
    float* __restrict__ out, int N, int K)
{
    __shared__ __align__(16) float As[16][128];
    __shared__ __align__(16) float Bs[16][64];
    const int m0 = blockIdx.x * 128;
    const int n0 = blockIdx.y * 64;
    const int tid = threadIdx.x;
    const int tx = tid & 15, ty = tid >> 4;

    u64 c2[4][4];
#pragma unroll
    for (int u = 0; u < 4; u++)
#pragma unroll
        for (int v = 0; v < 4; v++) c2[u][v] = 0ull;

    for (int kt = 0; kt < K; kt += 16) {
#pragma unroll
        for (int i = 0; i < 2; i++) {
            int f = tid + i * 256;
            int m = f >> 2, k4 = (f & 3) * 4;
            float4 a = *(const float4*)&A[(long)(m0 + m) * K + kt + k4];
            As[k4 + 0][m] = a.x; As[k4 + 1][m] = a.y;
            As[k4 + 2][m] = a.z; As[k4 + 3][m] = a.w;
        }
        {
            int n = tid >> 2, k4 = (tid & 3) * 4;
            float4 bv = *(const float4*)&Wt[(long)(n0 + n) * K + kt + k4];
            Bs[k4 + 0][n] = bv.x; Bs[k4 + 1][n] = bv.y;
            Bs[k4 + 2][n] = bv.z; Bs[k4 + 3][n] = bv.w;
        }
        __syncthreads();
#pragma unroll
        for (int kk = 0; kk < 16; kk++) {
            ulonglong2 aA = *(const ulonglong2*)&As[kk][ty * 8];
            ulonglong2 aB = *(const ulonglong2*)&As[kk][ty * 8 + 4];
            float4 bv = *(const float4*)&Bs[kk][tx * 4];
            u64 b0 = pack2(bv.x, bv.x);
            u64 b1 = pack2(bv.y, bv.y);
            u64 b2 = pack2(bv.z, bv.z);
            u64 b3 = pack2(bv.w, bv.w);
            ffma2(c2[0][0], aA.x, b0); ffma2(c2[0][1], aA.x, b1);
            ffma2(c2[0][2], aA.x, b2); ffma2(c2[0][3], aA.x, b3);
            ffma2(c2[1][0], aA.y, b0); ffma2(c2[1][1], aA.y, b1);
            ffma2(c2[1][2], aA.y, b2); ffma2(c2[1][3], aA.y, b3);
            ffma2(c2[2][0], aB.x, b0); ffma2(c2[2][1], aB.x, b1);
            ffma2(c2[2][2], aB.x, b2); ffma2(c2[2][3], aB.x, b3);
            ffma2(c2[3][0], aB.y, b0); ffma2(c2[3][1], aB.y, b1);
            ffma2(c2[3][2], aB.y, b2); ffma2(c2[3][3], aB.y, b3);
        }
        __syncthreads();
    }

    float4 bb = make_float4(0.f, 0.f, 0.f, 0.f);
    if (MODE >= 1) bb = *(const float4*)&bias[n0 + tx * 4];
#pragma unroll
    for (int u = 0; u < 4; u++) {
#pragma unroll
        for (int rsel = 0; rsel < 2; rsel++) {
            int row = m0 + ty * 8 + 2 * u + rsel;
            long rowoff = (long)row * N + n0 + tx * 4;
            float4 o;
            o.x = rsel ? hi2(c2[u][0]) : lo2(c2[u][0]);
            o.y = rsel ? hi2(c2[u][1]) : lo2(c2[u][1]);
            o.z = rsel ? hi2(c2[u][2]) : lo2(c2[u][2]);
            o.w = rsel ? hi2(c2[u][3]) : lo2(c2[u][3]);
            if (MODE >= 1) { o.x += bb.x; o.y += bb.y; o.z += bb.z; o.w += bb.w; }
            if (MODE == 1 || MODE == 3) {
                float4 rr = *(const float4*)&res[rowoff];
                o.x += rr.x; o.y += rr.y; o.z += rr.z; o.w += rr.w;
            }
            if (MODE == 2) {
                o.x = gelu_f(o.x); o.y = gelu_f(o.y);
                o.z = gelu_f(o.z); o.w = gelu_f(o.w);
            }
            *(float4*)&out[rowoff] = o;
        }
    }
}

// -------------------------- launch -----------------------------------------
extern "C" void kernel_launch(void* const* d_in, const int* in_sizes, int n_in,
                              void* d_out, int out_size)
{
    const float* x      = (const float*)d_in[0];
    const float* n1w    = (const float*)d_in[1];
    const float* n1b    = (const float*)d_in[2];
    const float* qkv_w  = (const float*)d_in[3];
    const float* proj_w = (const float*)d_in[4];
    const float* proj_b = (const float*)d_in[5];
    const float* n2w    = (const float*)d_in[6];
    const float* n2b    = (const float*)d_in[7];
    const float* fc1_w  = (const float*)d_in[8];
    const float* fc1_b  = (const float*)d_in[9];
    const float* fc2_w  = (const float*)d_in[10];
    const float* fc2_b  = (const float*)d_in[11];
    const float* pproj_w = (const float*)d_in[12];
    const float* pproj_b = (const float*)d_in[13];
    const float* pln1_w = (const float*)d_in[14];
    const float* pln1_b = (const float*)d_in[15];
    const float* pfc1_w = (const float*)d_in[16];
    const float* pfc1_b = (const float*)d_in[17];
    const float* pln2_w = (const float*)d_in[18];
    const float* pln2_b = (const float*)d_in[19];
    const float* pfc2_w = (const float*)d_in[20];
    const float* pfc2_b = (const float*)d_in[21];
    const float* pln3_w = (const float*)d_in[22];
    const float* pln3_b = (const float*)d_in[23];
    const float* pfc3_w = (const float*)d_in[24];
    const float* pfc3_b = (const float*)d_in[25];
    float* out = (float*)d_out;

    float *img, *qkvb, *att, *xo, *y, *hbuf, *pos;
    cudaGetSymbolAddress((void**)&img,  g_img);
    cudaGetSymbolAddress((void**)&qkvb, g_qkv);
    cudaGetSymbolAddress((void**)&att,  g_att);
    cudaGetSymbolAddress((void**)&xo,   g_xo);
    cudaGetSymbolAddress((void**)&y,    g_y);
    cudaGetSymbolAddress((void**)&hbuf, g_h);
    cudaGetSymbolAddress((void**)&pos,  g_pos);

    cudaFuncSetAttribute(attn_kernel,
                         cudaFuncAttributeMaxDynamicSharedMemorySize, ATTN_SMEM);

    pos_mlp_kernel<<<(2 * NPOS + 127) / 128, 128>>>(
        pproj_w, pproj_b, pln1_w, pln1_b, pfc1_w, pfc1_b,
        pln2_w, pln2_b, pfc2_w, pfc2_b, pln3_w, pln3_b, pfc3_w, pfc3_b, pos);
    ln_kernel<<<MROWS / 8, 256>>>(x, n1w, n1b, img);
    gemm_kernel<0><<<dim3(MROWS / 128, 576 / 64), 256>>>(
        img, qkv_w, nullptr, nullptr, qkvb, 576, 192);
    attn_kernel<<<256, ATHR, ATTN_SMEM>>>(qkvb, pos, att);
    gemm_kernel<1><<<dim3(MROWS / 128, 192 / 64), 256>>>(
        att, proj_w, proj_b, x, xo, 192, 192);
    ln_kernel<<<MROWS / 8, 256>>>(xo, n2w, n2b, y);
    gemm_kernel<2><<<dim3(MROWS / 128, HIDDEN / 64), 256>>>(
        y, fc1_w, fc1_b, nullptr, hbuf, HIDDEN, 192);
    gemm_kernel<3><<<dim3(MROWS / 128, 192 / 64), 256>>>(
        hbuf, fc2_w, fc2_b, xo, out, 192, HIDDEN);
}

// round 7
// speedup vs baseline: 1.7021x; 1.7021x over previous
#include <cuda_runtime.h>
#include <math.h>

// ---------------------------------------------------------------------------
// CATB axial attention block. fp32, FFMA2 (f32x2) everywhere hot.
// R7: attention = 12 warps, balanced rA=tid/rB=tid+384, chunked QK/AV phases
//     (16 indep FMA chains), no-max softmax, key-split SMEM-combined tail.
// ---------------------------------------------------------------------------

#define BATCH 2
#define HH 112
#define WW 112
#define CC 192
#define LL (HH * WW)          // 12544
#define MROWS (BATCH * LL)    // 25088
#define CB 96
#define HD_ 24
#define NTOK 784              // 112*7
#define NPOS 2899             // (2*112-1)*(2*7-1)
#define HIDDEN 768

typedef unsigned long long u64;

// -------------------------- scratch (device globals) -----------------------
__device__ float g_img[MROWS * CC];
__device__ float g_qkv[MROWS * 3 * CC];
__device__ float g_att[MROWS * CC];
__device__ float g_xo [MROWS * CC];
__device__ float g_y  [MROWS * CC];
__device__ float g_h  [MROWS * HIDDEN];
__device__ float g_pos[2 * NPOS * 4];

// -------------------------- f32x2 helpers ----------------------------------
__device__ __forceinline__ void ffma2(u64& c, u64 a, u64 b)
{
    asm("fma.rn.f32x2 %0, %1, %2, %0;" : "+l"(c) : "l"(a), "l"(b));
}
__device__ __forceinline__ u64 pack2(float lo, float hi)
{
    u64 r;
    asm("mov.b64 %0, {%1, %2};" : "=l"(r) : "f"(lo), "f"(hi));
    return r;
}
__device__ __forceinline__ float lo2(u64 v) { return __uint_as_float((unsigned)v); }
__device__ __forceinline__ float hi2(u64 v) { return __uint_as_float((unsigned)(v >> 32)); }

// -------------------------- LayerNorm over C=192 ---------------------------
__global__ __launch_bounds__(256) void ln_kernel(
    const float* __restrict__ in, const float* __restrict__ w,
    const float* __restrict__ b, float* __restrict__ out)
{
    int row = blockIdx.x * 8 + (threadIdx.x >> 5);
    if (row >= MROWS) return;
    int lane = threadIdx.x & 31;
    const float* p = in + (long)row * CC;
    float v[6];
    float s = 0.f, s2 = 0.f;
#pragma unroll
    for (int u = 0; u < 6; u++) {
        v[u] = p[lane + u * 32];
        s += v[u];
        s2 += v[u] * v[u];
    }
#pragma unroll
    for (int off = 16; off > 0; off >>= 1) {
        s  += __shfl_xor_sync(0xffffffffu, s,  off);
        s2 += __shfl_xor_sync(0xffffffffu, s2, off);
    }
    float mu  = s * (1.f / CC);
    float var = s2 * (1.f / CC) - mu * mu;
    float inv = rsqrtf(var + 1e-5f);
    float* q = out + (long)row * CC;
#pragma unroll
    for (int u = 0; u < 6; u++) {
        int c = lane + u * 32;
        q[c] = (v[u] - mu) * inv * w[c] + b[c];
    }
}

// -------------------------- rel-pos-bias MLP -------------------------------
__device__ __forceinline__ void ln6_relu(float* v, const float* w, const float* b)
{
    float mu = 0.f;
#pragma unroll
    for (int i = 0; i < 6; i++) mu += v[i];
    mu *= (1.f / 6.f);
    float var = 0.f;
#pragma unroll
    for (int i = 0; i < 6; i++) { float d = v[i] - mu; var += d * d; }
    var *= (1.f / 6.f);
    float inv = rsqrtf(var + 1e-5f);
#pragma unroll
    for (int i = 0; i < 6; i++)
        v[i] = fmaxf((v[i] - mu) * inv * w[i] + b[i], 0.f);
}

__global__ void pos_mlp_kernel(
    const float* __restrict__ proj_w, const float* __restrict__ proj_b,
    const float* __restrict__ ln1_w,  const float* __restrict__ ln1_b,
    const float* __restrict__ fc1_w,  const float* __restrict__ fc1_b,
    const float* __restrict__ ln2_w,  const float* __restrict__ ln2_b,
    const float* __restrict__ fc2_w,  const float* __restrict__ fc2_b,
    const float* __restrict__ ln3_w,  const float* __restrict__ ln3_b,
    const float* __restrict__ fc3_w,  const float* __restrict__ fc3_b,
    float* __restrict__ out)
{
    int idx = blockIdx.x * blockDim.x + threadIdx.x;
    if (idx >= 2 * NPOS) return;
    int br = idx / NPOS, r = idx - br * NPOS;
    int Hsp = br ? 7 : 112;
    int Wsp = br ? 112 : 7;
    int W2 = 2 * Wsp - 1;
    int a = r / W2, bcol = r - a * W2;
    float ph = (float)(a - (Hsp - 1));
    float pw = (float)(bcol - (Wsp - 1));

    float t[6], u[6];
#pragma unroll
    for (int o = 0; o < 6; o++)
        t[o] = proj_w[(br * 6 + o) * 2 + 0] * ph +
               proj_w[(br * 6 + o) * 2 + 1] * pw + proj_b[br * 6 + o];
    ln6_relu(t, ln1_w + br * 6, ln1_b + br * 6);
#pragma unroll
    for (int o = 0; o < 6; o++) {
        float s = fc1_b[br * 6 + o];
#pragma unroll
        for (int i = 0; i < 6; i++) s += fc1_w[br * 36 + o * 6 + i] * t[i];
        u[o] = s;
    }
    ln6_relu(u, ln2_w + br * 6, ln2_b + br * 6);
#pragma unroll
    for (int o = 0; o < 6; o++) {
        float s = fc2_b[br * 6 + o];
#pragma unroll
        for (int i = 0; i < 6; i++) s += fc2_w[br * 36 + o * 6 + i] * u[i];
        t[o] = s;
    }
    ln6_relu(t, ln3_w + br * 6, ln3_b + br * 6);
#pragma unroll
    for (int h = 0; h < 4; h++) {
        float s = fc3_b[br * 4 + h];
#pragma unroll
        for (int i = 0; i < 6; i++) s += fc3_w[br * 24 + h * 6 + i] * t[i];
        out[(br * NPOS + r) * 4 + h] = s;
    }
}

// -------------------------- attention --------------------------------------
// 256 blocks = (branch, window, head), 384 threads (12 warps).
// Main: thread t owns query rows t and t+384 (rows 0..767), full 784-key
// chunked pass. Tail rows 768..783: key-split over 24 half-warps, partial
// (e, O) summed in SMEM, combined by 384 threads (16 rows x 24 dims).
#define TAILP (16 * 24 * 25)
#define ATTN_SMEM ((2 * NTOK * HD_ + NPOS + NTOK + TAILP) * 4)
#define ATHR 384

__device__ __forceinline__ int row_to_l(int r, int br, int w16, int* rb)
{
    int Hsp = br ? 7 : 112;
    int Wsp = br ? 112 : 7;
    int W2  = 2 * Wsp - 1;
    int hi, wi, l;
    if (br == 0) { hi = r / 7;   wi = r - hi * 7;   l = hi * WW + w16 * 7 + wi; }
    else         { hi = r / 112; wi = r - hi * 112; l = (w16 * 7 + hi) * WW + wi; }
    *rb = (hi + Hsp - 1) * W2 + wi + Wsp - 1;
    return l;
}

__global__ __launch_bounds__(ATHR) void attn_kernel(
    const float* __restrict__ qkv, const float* __restrict__ pos,
    float* __restrict__ att_out)
{
    extern __shared__ float sm[];
    float* Ks = sm;                          // 784*24
    float* Vs = Ks + NTOK * HD_;             // 784*24
    float* Ps = Vs + NTOK * HD_;             // 2899
    int*   Rj = (int*)(Ps + NPOS);           // 784
    float* Tp = (float*)(Rj + NTOK);         // 16*24*25

    int bx   = blockIdx.x;
    int br   = bx >> 7;
    int rem  = bx & 127;
    int win  = rem >> 2;
    int head = rem & 3;
    int b    = win >> 4, w16 = win & 15;
    int tid  = threadIdx.x, lane = tid & 31, warp = tid >> 5;
    int cbase = br * CB + head * HD_;
    const float scale = 0.20412414523193154f; // 24^-0.5
    const int W2 = br ? (2 * WW - 1) : 13;

    // ---- stage K, V, pos column, rel-offsets into SMEM ----
    for (int idx = tid; idx < NTOK * HD_; idx += ATHR) {
        int j = idx / HD_, d = idx - j * HD_;
        int h, w;
        if (br == 0) { int hj = j / 7;   h = hj;           w = w16 * 7 + (j - hj * 7); }
        else         { int hj = j / 112; h = w16 * 7 + hj; w = j - hj * 112; }
        long base = ((long)(b * LL + h * WW + w)) * 576 + cbase + d;
        Ks[j * HD_ + d] = qkv[base + 192];
        Vs[j * HD_ + d] = qkv[base + 384];
    }
    for (int rr = tid; rr < NPOS; rr += ATHR)
        Ps[rr] = pos[(br * NPOS + rr) * 4 + head];
    for (int j = tid; j < NTOK; j += ATHR) {
        int hj, wj;
        if (br == 0) { hj = j / 7;   wj = j - hj * 7;   }
        else         { hj = j / 112; wj = j - hj * 112; }
        Rj[j] = hj * W2 + wj;
    }
    __syncthreads();

    // ---- main pass: rows rA = tid, rB = tid + 384 (both always valid) ----
    {
        int rbA, rbB;
        int lA = row_to_l(tid,       br, w16, &rbA);
        int lB = row_to_l(tid + 384, br, w16, &rbB);

        u64 qA[12], qB[12];
        {
            const float* qp = qkv + ((long)(b * LL + lA)) * 576 + cbase;
#pragma unroll
            for (int d = 0; d < 12; d++)
                qA[d] = pack2(qp[2 * d] * scale, qp[2 * d + 1] * scale);
        }
        {
            const float* qp = qkv + ((long)(b * LL + lB)) * 576 + cbase;
#pragma unroll
            for (int d = 0; d < 12; d++)
                qB[d] = pack2(qp[2 * d] * scale, qp[2 * d + 1] * scale);
        }

        float eA = 0.f, eB = 0.f;
        u64 OA[12], OB[12];
#pragma unroll
        for (int d = 0; d < 12; d++) { OA[d] = 0ull; OB[d] = 0ull; }

        for (int j0 = 0; j0 < NTOK; j0 += 8) {
            float pA[8], pB[8];
#pragma unroll
            for (int jj = 0; jj < 8; jj++) {
                int j = j0 + jj;
                const ulonglong2* kp = (const ulonglong2*)(Ks + j * HD_);
                u64 psA = 0ull, psB = 0ull;
#pragma unroll
                for (int i = 0; i < 6; i++) {
                    ulonglong2 kk = kp[i];
                    ffma2(psA, kk.x, qA[2 * i]);
                    ffma2(psA, kk.y, qA[2 * i + 1]);
                    ffma2(psB, kk.x, qB[2 * i]);
                    ffma2(psB, kk.y, qB[2 * i + 1]);
                }
                int roff = Rj[j];
                pA[jj] = __expf(lo2(psA) + hi2(psA) + Ps[rbA - roff]);
                pB[jj] = __expf(lo2(psB) + hi2(psB) + Ps[rbB - roff]);
            }
#pragma unroll
            for (int jj = 0; jj < 8; jj++) {
                int j = j0 + jj;
                eA += pA[jj]; eB += pB[jj];
                u64 pAd = pack2(pA[jj], pA[jj]);
                u64 pBd = pack2(pB[jj], pB[jj]);
                const ulonglong2* vp = (const ulonglong2*)(Vs + j * HD_);
#pragma unroll
                for (int i = 0; i < 6; i++) {
                    ulonglong2 vv = vp[i];
                    ffma2(OA[2 * i],     vv.x, pAd);
                    ffma2(OA[2 * i + 1], vv.y, pAd);
                    ffma2(OB[2 * i],     vv.x, pBd);
                    ffma2(OB[2 * i + 1], vv.y, pBd);
                }
            }
        }
        {
            float inv = 1.f / eA;
            float* o = att_out + ((long)(b * LL + lA)) * CC + cbase;
#pragma unroll
            for (int i = 0; i < 6; i++) {
                u64 a = OA[2 * i], c = OA[2 * i + 1];
                *(float4*)(o + i * 4) = make_float4(lo2(a) * inv, hi2(a) * inv,
                                                    lo2(c) * inv, hi2(c) * inv);
            }
        }
        {
            float inv = 1.f / eB;
            float* o = att_out + ((long)(b * LL + lB)) * CC + cbase;
#pragma unroll
            for (int i = 0; i < 6; i++) {
                u64 a = OB[2 * i], c = OB[2 * i + 1];
                *(float4*)(o + i * 4) = make_float4(lo2(a) * inv, hi2(a) * inv,
                                                    lo2(c) * inv, hi2(c) * inv);
            }
        }
    }

    // ---- tail rows 768..783: key-split over 24 half-warps ----
    {
        int c  = warp * 2 + (lane >> 4);      // chunk 0..23
        int r  = lane & 15;                   // tail row index 0..15
        int k0 = c * 33;
        int k1 = k0 + 33 < NTOK ? k0 + 33 : NTOK;

        int rbT;
        int lT = row_to_l(768 + r, br, w16, &rbT);
        u64 qT[12];
        {
            const float* qp = qkv + ((long)(b * LL + lT)) * 576 + cbase;
#pragma unroll
            for (int d = 0; d < 12; d++)
                qT[d] = pack2(qp[2 * d] * scale, qp[2 * d + 1] * scale);
        }
        float eT = 0.f;
        u64 OT[12];
#pragma unroll
        for (int d = 0; d < 12; d++) OT[d] = 0ull;

        for (int j = k0; j < k1; j++) {
            const ulonglong2* kp = (const ulonglong2*)(Ks + j * HD_);
            u64 ps = 0ull;
#pragma unroll
            for (int i = 0; i < 6; i++) {
                ulonglong2 kk = kp[i];
                ffma2(ps, kk.x, qT[2 * i]);
                ffma2(ps, kk.y, qT[2 * i + 1]);
            }
            float p = __expf(lo2(ps) + hi2(ps) + Ps[rbT - Rj[j]]);
            eT += p;
            u64 pd = pack2(p, p);
            const ulonglong2* vp = (const ulonglong2*)(Vs + j * HD_);
#pragma unroll
            for (int i = 0; i < 6; i++) {
                ulonglong2 vv = vp[i];
                ffma2(OT[2 * i],     vv.x, pd);
                ffma2(OT[2 * i + 1], vv.y, pd);
            }
        }
        float* tp = Tp + (r * 24 + c) * 25;
#pragma unroll
        for (int d = 0; d < 12; d++) {
            tp[2 * d]     = lo2(OT[d]);
            tp[2 * d + 1] = hi2(OT[d]);
        }
        tp[24] = eT;
    }
    __syncthreads();

    // ---- combine tail partials: 384 threads = 16 rows x 24 dims ----
    {
        int r = tid / 24, d = tid - r * 24;
        float so = 0.f, se = 0.f;
#pragma unroll
        for (int c = 0; c < 24; c++) {
            const float* tp = Tp + (r * 24 + c) * 25;
            so += tp[d];
            se += tp[24];
        }
        int rbT;
        int lT = row_to_l(768 + r, br, w16, &rbT);
        att_out[((long)(b * LL + lT)) * CC + cbase + d] = so / se;
    }
}

// -------------------------- SGEMM (NT) with FFMA2 --------------------------
// out[M,N] = A[M,K] @ W[N,K]^T. BM=128, BN=64, BK=16, 256 thr.
// Conflict-free SMEM layout; b duplicated into register pairs.
__device__ __forceinline__ float gelu_f(float x)
{
    return 0.5f * x * (1.f + erff(x * 0.7071067811865476f));
}

template <int MODE>
__global__ __launch_bounds__(256) void gemm_kernel(
    const float* __restrict__ A, const float* __restrict__ Wt,
    const float* __restrict__ bias, const float* __restrict__ res,
    float* __restrict__ out, int N, int K)
{
    __shared__ __align__(16) float As[16][128];
    __shared__ __align__(16) float Bs[16][64];
    const int m0 = blockIdx.x * 128;
    const int n0 = blockIdx.y * 64;
    const int tid = threadIdx.x;
    const int tx = tid & 15, ty = tid >> 4;

    u64 c2[4][4];
#pragma unroll
    for (int u = 0; u < 4; u++)
#pragma unroll
        for (int v = 0; v < 4; v++) c2[u][v] = 0ull;

    for (int kt = 0; kt < K; kt += 16) {
#pragma unroll
        for (int i = 0; i < 2; i++) {
            int f = tid + i * 256;
            int m = f >> 2, k4 = (f & 3) * 4;
            float4 a = *(const float4*)&A[(long)(m0 + m) * K + kt + k4];
            As[k4 + 0][m] = a.x; As[k4 + 1][m] = a.y;
            As[k4 + 2][m] = a.z; As[k4 + 3][m] = a.w;
        }
        {
            int n = tid >> 2, k4 = (tid & 3) * 4;
            float4 bv = *(const float4*)&Wt[(long)(n0 + n) * K + kt + k4];
            Bs[k4 + 0][n] = bv.x; Bs[k4 + 1][n] = bv.y;
            Bs[k4 + 2][n] = bv.z; Bs[k4 + 3][n] = bv.w;
        }
        __syncthreads();
#pragma unroll
        for (int kk = 0; kk < 16; kk++) {
            ulonglong2 aA = *(const ulonglong2*)&As[kk][ty * 8];
            ulonglong2 aB = *(const ulonglong2*)&As[kk][ty * 8 + 4];
            float4 bv = *(const float4*)&Bs[kk][tx * 4];
            u64 b0 = pack2(bv.x, bv.x);
            u64 b1 = pack2(bv.y, bv.y);
            u64 b2 = pack2(bv.z, bv.z);
            u64 b3 = pack2(bv.w, bv.w);
            ffma2(c2[0][0], aA.x, b0); ffma2(c2[0][1], aA.x, b1);
            ffma2(c2[0][2], aA.x, b2); ffma2(c2[0][3], aA.x, b3);
            ffma2(c2[1][0], aA.y, b0); ffma2(c2[1][1], aA.y, b1);
            ffma2(c2[1][2], aA.y, b2); ffma2(c2[1][3], aA.y, b3);
            ffma2(c2[2][0], aB.x, b0); ffma2(c2[2][1], aB.x, b1);
            ffma2(c2[2][2], aB.x, b2); ffma2(c2[2][3], aB.x, b3);
            ffma2(c2[3][0], aB.y, b0); ffma2(c2[3][1], aB.y, b1);
            ffma2(c2[3][2], aB.y, b2); ffma2(c2[3][3], aB.y, b3);
        }
        __syncthreads();
    }

    float4 bb = make_float4(0.f, 0.f, 0.f, 0.f);
    if (MODE >= 1) bb = *(const float4*)&bias[n0 + tx * 4];
#pragma unroll
    for (int u = 0; u < 4; u++) {
#pragma unroll
        for (int rsel = 0; rsel < 2; rsel++) {
            int row = m0 + ty * 8 + 2 * u + rsel;
            long rowoff = (long)row * N + n0 + tx * 4;
            float4 o;
            o.x = rsel ? hi2(c2[u][0]) : lo2(c2[u][0]);
            o.y = rsel ? hi2(c2[u][1]) : lo2(c2[u][1]);
            o.z = rsel ? hi2(c2[u][2]) : lo2(c2[u][2]);
            o.w = rsel ? hi2(c2[u][3]) : lo2(c2[u][3]);
            if (MODE >= 1) { o.x += bb.x; o.y += bb.y; o.z += bb.z; o.w += bb.w; }
            if (MODE == 1 || MODE == 3) {
                float4 rr = *(const float4*)&res[rowoff];
                o.x += rr.x; o.y += rr.y; o.z += rr.z; o.w += rr.w;
            }
            if (MODE == 2) {
                o.x = gelu_f(o.x); o.y = gelu_f(o.y);
                o.z = gelu_f(o.z); o.w = gelu_f(o.w);
            }
            *(float4*)&out[rowoff] = o;
        }
    }
}

// -------------------------- launch -----------------------------------------
extern "C" void kernel_launch(void* const* d_in, const int* in_sizes, int n_in,
                              void* d_out, int out_size)
{
    const float* x      = (const float*)d_in[0];
    const float* n1w    = (const float*)d_in[1];
    const float* n1b    = (const float*)d_in[2];
    const float* qkv_w  = (const float*)d_in[3];
    const float* proj_w = (const float*)d_in[4];
    const float* proj_b = (const float*)d_in[5];
    const float* n2w    = (const float*)d_in[6];
    const float* n2b    = (const float*)d_in[7];
    const float* fc1_w  = (const float*)d_in[8];
    const float* fc1_b  = (const float*)d_in[9];
    const float* fc2_w  = (const float*)d_in[10];
    const float* fc2_b  = (const float*)d_in[11];
    const float* pproj_w = (const float*)d_in[12];
    const float* pproj_b = (const float*)d_in[13];
    const float* pln1_w = (const float*)d_in[14];
    const float* pln1_b = (const float*)d_in[15];
    const float* pfc1_w = (const float*)d_in[16];
    const float* pfc1_b = (const float*)d_in[17];
    const float* pln2_w = (const float*)d_in[18];
    const float* pln2_b = (const float*)d_in[19];
    const float* pfc2_w = (const float*)d_in[20];
    const float* pfc2_b = (const float*)d_in[21];
    const float* pln3_w = (const float*)d_in[22];
    const float* pln3_b = (const float*)d_in[23];
    const float* pfc3_w = (const float*)d_in[24];
    const float* pfc3_b = (const float*)d_in[25];
    float* out = (float*)d_out;

    float *img, *qkvb, *att, *xo, *y, *hbuf, *pos;
    cudaGetSymbolAddress((void**)&img,  g_img);
    cudaGetSymbolAddress((void**)&qkvb, g_qkv);
    cudaGetSymbolAddress((void**)&att,  g_att);
    cudaGetSymbolAddress((void**)&xo,   g_xo);
    cudaGetSymbolAddress((void**)&y,    g_y);
    cudaGetSymbolAddress((void**)&hbuf, g_h);
    cudaGetSymbolAddress((void**)&pos,  g_pos);

    cudaFuncSetAttribute(attn_kernel,
                         cudaFuncAttributeMaxDynamicSharedMemorySize, ATTN_SMEM);

    pos_mlp_kernel<<<(2 * NPOS + 127) / 128, 128>>>(
        pproj_w, pproj_b, pln1_w, pln1_b, pfc1_w, pfc1_b,
        pln2_w, pln2_b, pfc2_w, pfc2_b, pln3_w, pln3_b, pfc3_w, pfc3_b, pos);
    ln_kernel<<<MROWS / 8, 256>>>(x, n1w, n1b, img);
    gemm_kernel<0><<<dim3(MROWS / 128, 576 / 64), 256>>>(
        img, qkv_w, nullptr, nullptr, qkvb, 576, 192);
    attn_kernel<<<256, ATHR, ATTN_SMEM>>>(qkvb, pos, att);
    gemm_kernel<1><<<dim3(MROWS / 128, 192 / 64), 256>>>(
        att, proj_w, proj_b, x, xo, 192, 192);
    ln_kernel<<<MROWS / 8, 256>>>(xo, n2w, n2b, y);
    gemm_kernel<2><<<dim3(MROWS / 128, HIDDEN / 64), 256>>>(
        y, fc1_w, fc1_b, nullptr, hbuf, HIDDEN, 192);
    gemm_kernel<3><<<dim3(MROWS / 128, 192 / 64), 256>>>(
        hbuf, fc2_w, fc2_b, xo, out, 192, HIDDEN);
}